// round 1
// baseline (speedup 1.0000x reference)
#include <cuda_runtime.h>
#include <cstdint>
#include <cstddef>

// ---------------------------------------------------------------------------
// Model_6863357739715: LSTM(B=2048,S=512,F=64,H=32) -> MLP(32->32->16->3)
//
// K1: xg[s][b][unit*4+gate] = sum_f x[b][s][f] * Wx[f][gate*32+unit]   (tf32 mma)
// K2: per-row recurrence over 512 steps with Wh in registers, then MLP head.
// ---------------------------------------------------------------------------

#define B_SZ   2048
#define S_SZ   512
#define F_SZ   64
#define H_SZ   32
#define G4     128                 // 4*H
#define M_TOT  (B_SZ * S_SZ)       // 1048576
#define MTILES (M_TOT / 64)        // 16384

// 512 MB scratch for the gate-packed input projections (fp32).
__device__ float g_xg_6863357739715[(size_t)S_SZ * B_SZ * G4];

// ---------------- helpers ----------------
__device__ __forceinline__ uint32_t f2tf32(float f) {
    uint32_t r;
    asm("cvt.rna.tf32.f32 %0, %1;" : "=r"(r) : "f"(f));
    return r;
}

__device__ __forceinline__ void mma_tf32(float d[4], const uint32_t a[4], const uint32_t b[2]) {
    asm volatile(
        "mma.sync.aligned.m16n8k8.row.col.f32.tf32.tf32.f32 "
        "{%0,%1,%2,%3}, {%4,%5,%6,%7}, {%8,%9}, {%0,%1,%2,%3};\n"
        : "+f"(d[0]), "+f"(d[1]), "+f"(d[2]), "+f"(d[3])
        : "r"(a[0]), "r"(a[1]), "r"(a[2]), "r"(a[3]), "r"(b[0]), "r"(b[1]));
}

__device__ __forceinline__ float sigm(float x) {
    return __fdividef(1.f, 1.f + __expf(-x));
}
__device__ __forceinline__ float tanh_(float x) {
    float ax = fabsf(x);
    float e  = __expf(-2.f * ax);
    float r  = __fdividef(1.f - e, 1.f + e);
    return copysignf(r, x);
}
__device__ __forceinline__ float lrelu(float x) {
    return x > 0.f ? x : 0.01f * x;
}

// ---------------------------------------------------------------------------
// K1: tall-skinny GEMM, M=1M, N=128, K=64, tf32 mma.sync m16n8k8.
// Block = 128 threads (4 warps), each warp computes an m16 x n128 tile.
// B (Wx, permuted to gate-packed columns) pre-swizzled once into smem as
// per-(ktile,ntile,lane) float2 fragments -> conflict-free LDS.64.
// ---------------------------------------------------------------------------
__global__ void __launch_bounds__(128) k1_proj(const float* __restrict__ x,
                                               const float* __restrict__ Wx) {
    __shared__ float2 sBf[8][16][32];   // [ktile][ntile][lane] = {b0,b1}, 32KB

    const int t = threadIdx.x;

    // Build B fragments once per block.
    for (int e = t; e < 8 * 16 * 32; e += 128) {
        int kt   = e >> 9;
        int nt   = (e >> 5) & 15;
        int lane = e & 31;
        int tg   = lane & 3;
        int gid  = lane >> 2;
        int k0   = kt * 8 + tg;         // b0 row (k), b1 at k0+4
        int n    = nt * 8 + gid;        // packed col: n = unit*4 + gate
        int g    = (n & 3) * 32 + (n >> 2);  // original column gate*32+unit
        float2 v;
        v.x = __uint_as_float(f2tf32(Wx[k0 * G4 + g]));
        v.y = __uint_as_float(f2tf32(Wx[(k0 + 4) * G4 + g]));
        sBf[kt][nt][lane] = v;
    }
    __syncthreads();

    const int warp = t >> 5;
    const int lane = t & 31;
    const int tg   = lane & 3;
    const int gid  = lane >> 2;

    for (int tile = blockIdx.x; tile < MTILES; tile += gridDim.x) {
        const int m0 = tile * 64 + warp * 16;

        // A fragments straight from gmem (rows m0+gid, m0+gid+8).
        uint32_t a[8][4];
        const float* xr0 = x + (size_t)(m0 + gid) * F_SZ;
        const float* xr8 = x + (size_t)(m0 + gid + 8) * F_SZ;
#pragma unroll
        for (int kt = 0; kt < 8; ++kt) {
            a[kt][0] = f2tf32(__ldg(xr0 + kt * 8 + tg));
            a[kt][1] = f2tf32(__ldg(xr8 + kt * 8 + tg));
            a[kt][2] = f2tf32(__ldg(xr0 + kt * 8 + tg + 4));
            a[kt][3] = f2tf32(__ldg(xr8 + kt * 8 + tg + 4));
        }

        float c[16][4];
#pragma unroll
        for (int nt = 0; nt < 16; ++nt) {
            c[nt][0] = 0.f; c[nt][1] = 0.f; c[nt][2] = 0.f; c[nt][3] = 0.f;
        }

#pragma unroll
        for (int kt = 0; kt < 8; ++kt) {
#pragma unroll
            for (int nt = 0; nt < 16; ++nt) {
                float2 bf = sBf[kt][nt][lane];
                uint32_t bb[2];
                bb[0] = __float_as_uint(bf.x);
                bb[1] = __float_as_uint(bf.y);
                mma_tf32(c[nt], a[kt], bb);
            }
        }

        // Store: row m -> (b = m/512, s = m%512); out layout [s][b][128].
        const int r0 = m0 + gid, r1 = r0 + 8;
        float* o0 = g_xg_6863357739715 +
                    ((size_t)(r0 & 511) * B_SZ + (r0 >> 9)) * G4 + 2 * tg;
        float* o1 = g_xg_6863357739715 +
                    ((size_t)(r1 & 511) * B_SZ + (r1 >> 9)) * G4 + 2 * tg;
#pragma unroll
        for (int nt = 0; nt < 16; ++nt) {
            *(float2*)(o0 + nt * 8) = make_float2(c[nt][0], c[nt][1]);
            *(float2*)(o1 + nt * 8) = make_float2(c[nt][2], c[nt][3]);
        }
    }
}

// ---------------------------------------------------------------------------
// K2: recurrence. Block = 64 threads (2 warps). Warp w handles batch rows
// 2w, 2w+1; lane k owns hidden unit k. Wh lives in 128 registers per lane.
// h broadcast via double-buffered smem + one __syncwarp per step.
// ---------------------------------------------------------------------------
__global__ void __launch_bounds__(64, 4) k2_recur(
    const float* __restrict__ Wh, const float* __restrict__ bvec,
    const float* __restrict__ W1, const float* __restrict__ b1v,
    const float* __restrict__ W2, const float* __restrict__ b2v,
    const float* __restrict__ Wo, const float* __restrict__ bov,
    float* __restrict__ out) {

    __shared__ float4 hs4[2][2][2][8];      // [warp][buf][row][8] = h as float4
    __shared__ float  a2s[2][2][16];        // MLP stage-2 activations

    const int lane = threadIdx.x & 31;
    const int wl   = threadIdx.x >> 5;
    const int w    = blockIdx.x * 2 + wl;
    const int row0 = w * 2;
    const int row1 = row0 + 1;

    // Wh packed per-lane: wh[j][g] = Wh[j][g*32 + lane]
    float wh[H_SZ][4];
#pragma unroll
    for (int j = 0; j < H_SZ; ++j) {
#pragma unroll
        for (int g = 0; g < 4; ++g)
            wh[j][g] = __ldg(Wh + j * G4 + g * 32 + lane);
    }
    float bz[4];
#pragma unroll
    for (int g = 0; g < 4; ++g) bz[g] = __ldg(bvec + g * 32 + lane);

    // init h buffers to 0
    ((float*)&hs4[wl][0][0][0])[lane] = 0.f;
    ((float*)&hs4[wl][0][1][0])[lane] = 0.f;
    __syncwarp();

    const float4* xg4 = (const float4*)g_xg_6863357739715;
    const size_t ix0 = (size_t)row0 * 32 + lane;   // float4 index at s=0
    const size_t ix1 = (size_t)row1 * 32 + lane;
    const size_t sstep = (size_t)B_SZ * 32;        // float4 per timestep

    float c0 = 0.f, h0 = 0.f, c1 = 0.f, h1 = 0.f;
    float4 xA = __ldg(&xg4[ix0]);
    float4 xB = __ldg(&xg4[ix1]);
    int p = 0;

#pragma unroll 1
    for (int s = 0; s < S_SZ; ++s) {
        const int sn = (s + 1 < S_SZ) ? (s + 1) : (S_SZ - 1);
        float4 nA = __ldg(&xg4[ix0 + (size_t)sn * sstep]);
        float4 nB = __ldg(&xg4[ix1 + (size_t)sn * sstep]);

        float zi0 = xA.x + bz[0], zf0 = xA.y + bz[1], zg0 = xA.z + bz[2], zo0 = xA.w + bz[3];
        float zi1 = xB.x + bz[0], zf1 = xB.y + bz[1], zg1 = xB.z + bz[2], zo1 = xB.w + bz[3];

        const float4* hp0 = &hs4[wl][p][0][0];
        const float4* hp1 = &hs4[wl][p][1][0];

#define ACC4(HV, JJ)                                                        \
        do {                                                                \
            zi0 += (HV##0) * wh[JJ][0]; zf0 += (HV##0) * wh[JJ][1];         \
            zg0 += (HV##0) * wh[JJ][2]; zo0 += (HV##0) * wh[JJ][3];         \
            zi1 += (HV##1) * wh[JJ][0]; zf1 += (HV##1) * wh[JJ][1];         \
            zg1 += (HV##1) * wh[JJ][2]; zo1 += (HV##1) * wh[JJ][3];         \
        } while (0)

#pragma unroll
        for (int j4 = 0; j4 < 8; ++j4) {
            const float4 hv0 = hp0[j4];
            const float4 hv1 = hp1[j4];
            const int j = j4 * 4;
            { const float vx0 = hv0.x, vx1 = hv1.x; ACC4(vx, j + 0); }
            { const float vy0 = hv0.y, vy1 = hv1.y; ACC4(vy, j + 1); }
            { const float vz0 = hv0.z, vz1 = hv1.z; ACC4(vz, j + 2); }
            { const float vw0 = hv0.w, vw1 = hv1.w; ACC4(vw, j + 3); }
        }
#undef ACC4

        // gates (i, f, g, o)
        {
            float ig = sigm(zi0), fg = sigm(zf0), gg = tanh_(zg0), og = sigm(zo0);
            c0 = fg * c0 + ig * gg;
            h0 = og * tanh_(c0);
        }
        {
            float ig = sigm(zi1), fg = sigm(zf1), gg = tanh_(zg1), og = sigm(zo1);
            c1 = fg * c1 + ig * gg;
            h1 = og * tanh_(c1);
        }

        p ^= 1;
        ((float*)&hs4[wl][p][0][0])[lane] = h0;
        ((float*)&hs4[wl][p][1][0])[lane] = h1;
        __syncwarp();

        xA = nA; xB = nB;
    }

    // ------------- MLP head -------------
    const float* hf0 = (const float*)&hs4[wl][p][0][0];
    const float* hf1 = (const float*)&hs4[wl][p][1][0];

    float a0 = __ldg(b1v + lane);
    float a1r = a0;
#pragma unroll
    for (int j = 0; j < 32; ++j) {
        const float wv = __ldg(W1 + j * 32 + lane);
        a0  += hf0[j] * wv;
        a1r += hf1[j] * wv;
    }
    a0 = lrelu(a0); a1r = lrelu(a1r);

    // stash a1 in the other h buffer
    ((float*)&hs4[wl][p ^ 1][0][0])[lane] = a0;
    ((float*)&hs4[wl][p ^ 1][1][0])[lane] = a1r;
    __syncwarp();

    if (lane < 16) {
        const float* af0 = (const float*)&hs4[wl][p ^ 1][0][0];
        const float* af1 = (const float*)&hs4[wl][p ^ 1][1][0];
        float s0 = __ldg(b2v + lane);
        float s1 = s0;
#pragma unroll
        for (int j = 0; j < 32; ++j) {
            const float wv = __ldg(W2 + j * 16 + lane);
            s0 += af0[j] * wv;
            s1 += af1[j] * wv;
        }
        a2s[wl][0][lane] = lrelu(s0);
        a2s[wl][1][lane] = lrelu(s1);
    }
    __syncwarp();

    if (lane < 3) {
        float o0v = __ldg(bov + lane);
        float o1v = o0v;
#pragma unroll
        for (int j = 0; j < 16; ++j) {
            const float wv = __ldg(Wo + j * 3 + lane);
            o0v += a2s[wl][0][j] * wv;
            o1v += a2s[wl][1][j] * wv;
        }
        out[row0 * 3 + lane] = o0v;
        out[row1 * 3 + lane] = o1v;
    }
}

// ---------------------------------------------------------------------------
extern "C" void kernel_launch(void* const* d_in, const int* in_sizes, int n_in,
                              void* d_out, int out_size) {
    (void)in_sizes; (void)n_in; (void)out_size;
    const float* x    = (const float*)d_in[0];
    const float* Wx   = (const float*)d_in[1];
    const float* Wh   = (const float*)d_in[2];
    const float* bvec = (const float*)d_in[3];
    const float* W1   = (const float*)d_in[4];
    const float* b1v  = (const float*)d_in[5];
    const float* W2   = (const float*)d_in[6];
    const float* b2v  = (const float*)d_in[7];
    const float* Wo   = (const float*)d_in[8];
    const float* bov  = (const float*)d_in[9];

    k1_proj<<<2048, 128>>>(x, Wx);
    k2_recur<<<512, 64>>>(Wh, bvec, W1, b1v, W2, b2v, Wo, bov, (float*)d_out);
}